// round 12
// baseline (speedup 1.0000x reference)
#include <cuda_runtime.h>

#define NH 192            // nH = nW = 193 - 2 + 1
#define HG 193            // grid H/W
#define MD 64             // vec dim m
#define NTCP 36           // tc row pitch (floats): conflict-free across (i,jh) rows

// Scratch (allocation-free rule: __device__ globals)
__device__ float g_x[NH * NH * MD];      // x = win_avg(grid) @ M^T, 9.4 MB

// ---- packed f32x2 helpers -------------------------------------------------
__device__ __forceinline__ unsigned long long pk(float x, float y) {
    unsigned long long r;
    asm("mov.b64 %0, {%1, %2};" : "=l"(r) : "f"(x), "f"(y));
    return r;
}
__device__ __forceinline__ float2 upk(unsigned long long v) {
    float2 t;
    asm("mov.b64 {%0, %1}, %2;" : "=f"(t.x), "=f"(t.y) : "l"(v));
    return t;
}
__device__ __forceinline__ unsigned long long fma2(unsigned long long a,
                                                   unsigned long long b,
                                                   unsigned long long c) {
    unsigned long long r;
    asm("fma.rn.f32x2 %0, %1, %2, %3;" : "=l"(r) : "l"(a), "l"(b), "l"(c));
    return r;
}

// ---- cp.async helpers -------------------------------------------------------
__device__ __forceinline__ void cp_async16(unsigned dst_smem, const void* src) {
    asm volatile("cp.async.cg.shared.global [%0], [%1], 16;"
                 :: "r"(dst_smem), "l"(src) : "memory");
}
__device__ __forceinline__ void cp_commit() {
    asm volatile("cp.async.commit_group;" ::: "memory");
}
template <int N>
__device__ __forceinline__ void cp_wait() {
    asm volatile("cp.async.wait_group %0;" :: "n"(N) : "memory");
}

// ---------------------------------------------------------------------------
// Kernel 1: x[b, j] = sum_l wavg[b, l] * M[j, l]   (R9 version — proven)
// ---------------------------------------------------------------------------
__global__ void __launch_bounds__(256) x_prep(const float* __restrict__ grid,
                                              const float* __restrict__ Mw) {
    __shared__ __align__(16) float sbuf[66 * 64];

    int t  = threadIdx.x;
    int q  = t >> 6;
    int jl = t & 63;

    int bid    = blockIdx.x;
    int k1     = bid / 6;
    int k2base = (bid % 6) * 32;

    for (int e = t; e < 4096; e += 256) sbuf[(e >> 6) * 66 + (e & 63)] = Mw[e];
    __syncthreads();
    unsigned long long Mp[32];
#pragma unroll
    for (int l = 0; l < 32; l++)
        Mp[l] = pk(sbuf[jl * 66 + 2 * l], sbuf[jl * 66 + 2 * l + 1]);
    __syncthreads();

#pragma unroll
    for (int r = 0; r < 8; r++) {
        int e   = t + 256 * r;
        int row = e >> 6;
        int col = e & 63;
        const float* g00 = grid + ((k1 * HG + k2base + row) * MD) + col;
        sbuf[row * 64 + col] = 0.25f * (g00[0] + g00[MD] +
                                        g00[HG * MD] + g00[HG * MD + MD]);
    }
    __syncthreads();

#pragma unroll
    for (int r = 0; r < 8; r++) {
        int k2r = q + 4 * r;
        const ulonglong2* w2 = reinterpret_cast<const ulonglong2*>(&sbuf[k2r * 64]);
        unsigned long long a0 = 0ULL, a1 = 0ULL;
#pragma unroll
        for (int l = 0; l < 16; l++) {
            ulonglong2 w = w2[l];
            a0 = fma2(Mp[2 * l],     w.x, a0);
            a1 = fma2(Mp[2 * l + 1], w.y, a1);
        }
        float2 f0 = upk(a0), f1 = upk(a1);
        g_x[(k1 * NH + k2base + k2r) * MD + jl] = (f0.x + f0.y) + (f1.x + f1.y);
    }
}

// ---------------------------------------------------------------------------
// Main kernel (Chebyshev, R9-proven recurrence + R11 structure):
//   Nk[b,i] = sum_j x[b,j] * P[i,j] * cos(2pi*k1/T) * cos(2pi*k2/T)
//   d_{k+1} = 2cos(theta)*d_k - d_{k-1};  state: Dc = d_k, Dn = -d_{k-1}
//   step: tmp = fma(tc, Dc, Dn); Dn = Dc ^ SIGN; Dc = tmp  (XOR on ALU pipe)
//
// 512 threads: t = (k1sub<<7) | (i<<1) | jh.  CTA = 4 k1 x 64 k2.
// Grid (3, 48) = 144 CTAs = one wave.  All cos computed inline (no table).
// State: Dc[16] + Dn[16] = 64 regs; tc (= +2cos theta) in smem (pitch 36).
// x staged in 16-k2 blocks via cp.async double buffer (R9 pattern — proven).
// ---------------------------------------------------------------------------
__global__ void __launch_bounds__(512, 1) main_kernel(const float* __restrict__ P,
                                                      float* __restrict__ out) {
    __shared__ __align__(16) float tcs[128 * NTCP];      // 18.4 KB, +2cos(theta)
    __shared__ __align__(16) float xs[2][16][4][64];     // 32 KB

    const unsigned long long SGN = 0x8000000080000000ULL;

    int t      = threadIdx.x;
    int jh     = t & 1;
    int i      = (t >> 1) & 63;
    int k1sub  = t >> 7;                 // 0..3
    int k1base = blockIdx.y * 4;
    int k1     = k1base + k1sub;
    int k2s    = blockIdx.x * 64;

    unsigned xs_base = (unsigned)__cvta_generic_to_shared(&xs[0][0][0][0]);

    // stage one 16-k2 block of x (R9 pattern, verbatim)
    auto issue_block = [&](int b) {
        int kb = k2s + b * 16;
        unsigned dbase = xs_base + ((b & 1) ? 16384u : 0u);
#pragma unroll
        for (int h = 0; h < 2; h++) {
            int f  = t + 512 * h;                        // 0..1023
            int s  = f >> 8;                             // k1 row 0..3
            int rm = f & 255;
            int r  = rm >> 4;                            // k2 offset 0..15
            int j4 = rm & 15;
            const float4* src = reinterpret_cast<const float4*>(g_x) +
                                (((k1base + s) * NH + kb + r) << 4) + j4;
            unsigned dst = dbase + (((r * 4 + s) * 64 + j4 * 4) << 2);
            cp_async16(dst, src);
        }
        cp_commit();
    };

    issue_block(0);          // overlap staging with the cosf-heavy prologue
    issue_block(1);

    // ---- prologue: inline cos; build Dc / Dn and tc ----
    unsigned long long Dc[16], Dn[16];
    {
        const float TWO_PI = 6.2831853071795864769f;
        float k1f = (float)k1;
        float kaf = (float)k2s;
        float kbf = (float)(k2s - 1);                    // cosf(-x) == cosf(x)
        int   jb  = jh * 32;
        float* trow = &tcs[(i * 2 + jh) * NTCP];
#pragma unroll
        for (int p = 0; p < 8; p++) {
            float4 pp = reinterpret_cast<const float4*>(P)[i * 16 + jh * 8 + p];
            float dcv[4], dnv[4], tcv[4];
            float pv[4] = {pp.x, pp.y, pp.z, pp.w};
#pragma unroll
            for (int c = 0; c < 4; c++) {
                float Tj = (float)(i * MD + jb + p * 4 + c + 2);
                float e  = cosf(TWO_PI * k1f / Tj) * pv[c];   // E = P * cos1
                dcv[c] =  e * cosf(TWO_PI * kaf / Tj);        //  d_{k2s}
                dnv[c] = -e * cosf(TWO_PI * kbf / Tj);        // -d_{k2s-1}
                tcv[c] = 2.0f * cosf(TWO_PI / Tj);            // +2 cos(theta)
            }
            Dc[2 * p]     = pk(dcv[0], dcv[1]);
            Dc[2 * p + 1] = pk(dcv[2], dcv[3]);
            Dn[2 * p]     = pk(dnv[0], dnv[1]);
            Dn[2 * p + 1] = pk(dnv[2], dnv[3]);
            if (k1sub == 0)
                *reinterpret_cast<float4*>(trow + p * 4) =
                    make_float4(tcv[0], tcv[1], tcv[2], tcv[3]);
        }
    }

    // ---- main loop: 4 blocks x 16 k2 ----
    for (int b = 0; b < 4; b++) {
        if (b >= 1) {
            __syncthreads();             // readers of buf[(b+1)&1] (block b-1) done
            if (b + 1 < 4) issue_block(b + 1);
        }
        if (b + 1 < 4) cp_wait<1>(); else cp_wait<0>();
        __syncthreads();                 // block b (+ b==0: tcs) visible to all

        const float* xbase = &xs[b & 1][0][k1sub][jh * 32];
        const ulonglong2* trow =
            reinterpret_cast<const ulonglong2*>(&tcs[(i * 2 + jh) * NTCP]);

#pragma unroll 4
        for (int r = 0; r < 16; r++) {
            const ulonglong2* xr =
                reinterpret_cast<const ulonglong2*>(xbase + r * 256);
            unsigned long long a0 = 0ULL, a1 = 0ULL;
#pragma unroll
            for (int p = 0; p < 8; p++) {
                ulonglong2 xv = xr[p];                   // conflict-free LDS.128
                a0 = fma2(Dc[2 * p],     xv.x, a0);
                a1 = fma2(Dc[2 * p + 1], xv.y, a1);
            }
            // Chebyshev step: tmp = tc*Dc + Dn; Dn = Dc^SGN (ALU); Dc = tmp
#pragma unroll
            for (int p = 0; p < 8; p++) {
                ulonglong2 tc = trow[p];
                unsigned long long t0 = fma2(tc.x, Dc[2 * p],     Dn[2 * p]);
                unsigned long long t1 = fma2(tc.y, Dc[2 * p + 1], Dn[2 * p + 1]);
                Dn[2 * p]     = Dc[2 * p]     ^ SGN;
                Dn[2 * p + 1] = Dc[2 * p + 1] ^ SGN;
                Dc[2 * p]     = t0;
                Dc[2 * p + 1] = t1;
            }
            float2 f0 = upk(a0), f1 = upk(a1);
            float part = (f0.x + f0.y) + (f1.x + f1.y);
            part += __shfl_xor_sync(0xFFFFFFFFu, part, 1);
            if (jh == 0) {
                int k2 = k2s + b * 16 + r;
                out[(k1 * NH + k2) * MD + i] = part;
            }
        }
    }
}

// ---------------------------------------------------------------------------
// Launch: inputs in metadata order: grid [193,193,64], M_weight [64,64], P [64,64]
// ---------------------------------------------------------------------------
extern "C" void kernel_launch(void* const* d_in, const int* in_sizes, int n_in,
                              void* d_out, int out_size) {
    const float* grid = (const float*)d_in[0];
    const float* Mw   = (const float*)d_in[1];
    const float* P    = (const float*)d_in[2];
    float* out        = (float*)d_out;

    x_prep<<<1152, 256>>>(grid, Mw);
    main_kernel<<<dim3(3, 48), 512>>>(P, out);
}